// round 4
// baseline (speedup 1.0000x reference)
#include <cuda_runtime.h>
#include <cuda_bf16.h>
#include <cstdint>

#define NB 65536
#define FEAT 261
#define HID 128
#define KSTEPS 17                 // K padded to 272
#define NTHREAD 512
#define ROWS_CTA 128
#define NCTA (NB / ROWS_CTA)      // 512
#define NTILES_HALF 8

// W fragment scratch, hi/lo interleaved: [kstep][tile16][lane32][4 u32 = bh0,bh1,bl0,bl1]
#define WFRAG_U32 (KSTEPS * 16 * 32 * 4)      // 34816 u32 = 139264 B
__device__ __align__(16) uint32_t g_wfrag[WFRAG_U32];

// ---- smem layout (bytes) ----
#define PARAM_FLOATS 1344
#define OFF_WF   (PARAM_FLOATS * 4)              // 5376
#define OFF_XHI  (OFF_WF + WFRAG_U32 * 4)        // 144640
#define XS_U32   76                              // row stride in u32 (152 bf16; conflict-free for ldmatrix)
#define XBUF_B   (128 * XS_U32 * 4)              // 38912
#define OFF_XLO  (OFF_XHI + XBUF_B)              // 183552
#define SMEM_BYTES (OFF_XLO + XBUF_B)            // 222464

// float indices inside params region
#define P_W0   0
#define P_W1   288
#define P_W2   554
#define P_LEAF 830
#define P_BC1  896
#define P_WC2  1024
#define P_B    1152
#define P_VBUF 1160   // 128 row partials

// ======================= prep: Wc1 -> interleaved bf16 hi/lo fragments =======================
__global__ void __launch_bounds__(256) prep_w(const float* __restrict__ Wc1) {
    int idx = blockIdx.x * 256 + threadIdx.x;
    if (idx >= WFRAG_U32) return;
    int j    = idx & 3;            // 0,1: hi regs b0,b1 ; 2,3: lo regs b0,b1
    int lane = (idx >> 2) & 31;
    int t    = (idx >> 7) & 15;
    int s    = idx >> 11;
    int n = t * 8 + (lane >> 2);
    int k = s * 16 + (j & 1) * 8 + (lane & 3) * 2;
    float v0 = (k     < FEAT) ? Wc1[k * HID + n]       : 0.0f;
    float v1 = (k + 1 < FEAT) ? Wc1[(k + 1) * HID + n] : 0.0f;
    __nv_bfloat16 h0 = __float2bfloat16(v0), h1 = __float2bfloat16(v1);
    if (j < 2) {
        g_wfrag[idx] = ((uint32_t)__bfloat16_as_ushort(h1) << 16) | __bfloat16_as_ushort(h0);
    } else {
        __nv_bfloat16 l0 = __float2bfloat16(v0 - __bfloat162float(h0));
        __nv_bfloat16 l1 = __float2bfloat16(v1 - __bfloat162float(h1));
        g_wfrag[idx] = ((uint32_t)__bfloat16_as_ushort(l1) << 16) | __bfloat16_as_ushort(l0);
    }
}

// ======================= helpers =======================
__device__ __forceinline__ uint32_t smem_u32(const void* p) {
    uint32_t a;
    asm("{ .reg .u64 t; cvta.to.shared.u64 t, %1; cvt.u32.u64 %0, t; }" : "=r"(a) : "l"(p));
    return a;
}
__device__ __forceinline__ float warpsum(float v) {
    v += __shfl_xor_sync(0xffffffffu, v, 16);
    v += __shfl_xor_sync(0xffffffffu, v, 8);
    v += __shfl_xor_sync(0xffffffffu, v, 4);
    v += __shfl_xor_sync(0xffffffffu, v, 2);
    v += __shfl_xor_sync(0xffffffffu, v, 1);
    return v;
}
__device__ __forceinline__ float sigmoidf_fast(float g) { return 1.0f / (1.0f + __expf(-g)); }

__device__ __forceinline__ uint32_t pack_hi(float v0, float v1, uint32_t& lo) {
    __nv_bfloat16 h0 = __float2bfloat16(v0), h1 = __float2bfloat16(v1);
    __nv_bfloat16 l0 = __float2bfloat16(v0 - __bfloat162float(h0));
    __nv_bfloat16 l1 = __float2bfloat16(v1 - __bfloat162float(h1));
    lo = ((uint32_t)__bfloat16_as_ushort(l1) << 16) | __bfloat16_as_ushort(l0);
    return ((uint32_t)__bfloat16_as_ushort(h1) << 16) | __bfloat16_as_ushort(h0);
}

#define MMA16816(c, a0, a1, a2, a3, b0, b1) \
    asm volatile("mma.sync.aligned.m16n8k16.row.col.f32.bf16.bf16.f32 " \
        "{%0,%1,%2,%3}, {%4,%5,%6,%7}, {%8,%9}, {%0,%1,%2,%3};" \
        : "+f"((c)[0]), "+f"((c)[1]), "+f"((c)[2]), "+f"((c)[3]) \
        : "r"(a0), "r"(a1), "r"(a2), "r"(a3), "r"(b0), "r"(b1))

#define LDMATRIX_X4(r0, r1, r2, r3, addr) \
    asm volatile("ldmatrix.sync.aligned.m8n8.x4.shared.b16 {%0,%1,%2,%3}, [%4];" \
        : "=r"(r0), "=r"(r1), "=r"(r2), "=r"(r3) : "r"(addr))

// ======================= main fused kernel =======================
__global__ void __launch_bounds__(NTHREAD, 1)
ac_main(const float* __restrict__ x,
        const float* __restrict__ w0, const float* __restrict__ b0,
        const float* __restrict__ w1, const float* __restrict__ b1,
        const float* __restrict__ w2, const float* __restrict__ b2,
        const float* __restrict__ leaf,
        const float* __restrict__ bc1,
        const float* __restrict__ Wc2, const float* __restrict__ bc2,
        float* __restrict__ p_out, float* __restrict__ v_out)
{
    extern __shared__ char smem[];
    float* sp = (float*)smem;
    const uint32_t smem_base = smem_u32(smem);
    const int tid  = threadIdx.x;
    const int lane = tid & 31;
    const int warp = tid >> 5;
    const int row0 = blockIdx.x * ROWS_CTA;

    // ---- stage params + W fragments ----
    for (int i = tid; i < 288; i += NTHREAD) sp[P_W0 + i] = (i < FEAT) ? w0[i] : 0.0f;
    for (int i = tid; i < 266; i += NTHREAD) sp[P_W1 + i] = w1[i];
    for (int i = tid; i < 276; i += NTHREAD) sp[P_W2 + i] = w2[i];
    if (tid < 64)  sp[P_LEAF + tid] = leaf[tid];
    if (tid < 128) sp[P_BC1 + tid]  = bc1[tid];
    if (tid < 128) sp[P_WC2 + tid]  = Wc2[tid];
    if (tid < 128) sp[P_VBUF + tid] = 0.0f;
    if (tid == 0) {
        sp[P_B + 0] = b0[0];
        sp[P_B + 1] = b1[0]; sp[P_B + 2] = b1[1];
        sp[P_B + 3] = b2[0]; sp[P_B + 4] = b2[1]; sp[P_B + 5] = b2[2]; sp[P_B + 6] = b2[3];
        sp[P_B + 7] = bc2[0];
    }
    {
        const uint4* g = (const uint4*)g_wfrag;
        uint4* s = (uint4*)(smem + OFF_WF);
        #pragma unroll 4
        for (int i = tid; i < WFRAG_U32 / 4; i += NTHREAD) s[i] = g[i];
    }
    __syncthreads();

    // ================= decision tree (exact fp32): 8 rows per warp =================
    {
        const int trow0 = row0 + warp * 8;
        #pragma unroll 1
        for (int r = 0; r < 8; r++) {
            const int row = trow0 + r;
            const float* xrow = x + (size_t)row * FEAT;
            float part = 0.0f;
            #pragma unroll
            for (int k = 0; k < 9; k++) {
                int f = lane + 32 * k;
                if (f < FEAT) part = fmaf(xrow[f], sp[P_W0 + f], part);
            }
            float gate = warpsum(part) + sp[P_B + 0];
            float cum  = sigmoidf_fast(gate);
            int node   = (gate >= 0.0f) ? 1 : 0;
            {
                const float* wr = sp + P_W1 + node * 133;
                const int s1 = 5 + node * 128;
                part = (lane < 5) ? xrow[lane] * wr[lane] : 0.0f;
                #pragma unroll
                for (int k = 0; k < 4; k++) { int j = lane + 32 * k; part = fmaf(xrow[s1 + j], wr[5 + j], part); }
                gate = warpsum(part) + sp[P_B + 1 + node];
                cum *= sigmoidf_fast(gate);
                node = node * 2 + ((gate >= 0.0f) ? 1 : 0);
            }
            {
                const float* wr = sp + P_W2 + node * 69;
                const int s2 = 5 + node * 64;
                part = (lane < 5) ? xrow[lane] * wr[lane] : 0.0f;
                #pragma unroll
                for (int k = 0; k < 2; k++) { int j = lane + 32 * k; part = fmaf(xrow[s2 + j], wr[5 + j], part); }
                gate = warpsum(part) + sp[P_B + 3 + node];
                cum *= sigmoidf_fast(gate);
                node = node * 2 + ((gate >= 0.0f) ? 1 : 0);
            }
            if (lane < 8)
                p_out[(size_t)row * 8 + lane] = cum * sp[P_LEAF + node * 8 + lane];
        }
    }

    // ================= critic GEMM: 2 K-chunks, smem-converted A, ldmatrix =================
    const int mt = warp >> 1;          // m-tile 0..7
    const int nh = warp & 1;           // n-half 0/1
    uint32_t* xhi = (uint32_t*)(smem + OFF_XHI);
    uint32_t* xlo = (uint32_t*)(smem + OFF_XLO);
    const uint32_t a_hi_base = smem_base + OFF_XHI +
        (uint32_t)(((mt * 16 + (lane & 15)) * XS_U32 + ((lane >> 4) & 1) * 4) * 4);
    const uint32_t a_lo_base = a_hi_base + XBUF_B;

    float acc[NTILES_HALF][4];
    #pragma unroll
    for (int t = 0; t < NTILES_HALF; t++)
        #pragma unroll
        for (int j = 0; j < 4; j++) acc[t][j] = 0.0f;

    #pragma unroll 1
    for (int c = 0; c < 2; c++) {
        const int k0   = c * 144;
        const int klen = c ? 128 : 144;
        const int nst  = c ? 8 : 9;

        // ---- convert x chunk -> smem bf16 hi/lo ----
        const int nquad = 128 * (klen >> 2);
        #pragma unroll 1
        for (int idx = tid; idx < nquad; idx += NTHREAD) {
            const int row = idx / (klen >> 2);
            const int q   = idx - row * (klen >> 2);
            const int gk  = k0 + q * 4;
            const float* xr = x + (size_t)(row0 + row) * FEAT + gk;
            float v0 = (gk     < FEAT) ? xr[0] : 0.0f;
            float v1 = (gk + 1 < FEAT) ? xr[1] : 0.0f;
            float v2 = (gk + 2 < FEAT) ? xr[2] : 0.0f;
            float v3 = (gk + 3 < FEAT) ? xr[3] : 0.0f;
            uint32_t l0, l1;
            uint32_t h0 = pack_hi(v0, v1, l0);
            uint32_t h1 = pack_hi(v2, v3, l1);
            const int o = row * XS_U32 + q * 2;
            xhi[o] = h0; xhi[o + 1] = h1;
            xlo[o] = l0; xlo[o + 1] = l1;
        }
        __syncthreads();

        // ---- MMA over this chunk's k-steps ----
        #pragma unroll 1
        for (int sk = 0; sk < nst; sk++) {
            uint32_t ah0, ah1, ah2, ah3, al0, al1, al2, al3;
            LDMATRIX_X4(ah0, ah1, ah2, ah3, a_hi_base + (uint32_t)(sk * 32));
            LDMATRIX_X4(al0, al1, al2, al3, a_lo_base + (uint32_t)(sk * 32));
            const int s = c * 9 + sk;
            const uint4* bp = (const uint4*)(smem + OFF_WF) + ((s * 16 + nh * 8) * 32 + lane);
            #pragma unroll
            for (int t = 0; t < NTILES_HALF; t++) {
                const uint4 b = bp[t * 32];
                MMA16816(acc[t], ah0, ah1, ah2, ah3, b.x, b.y);
                MMA16816(acc[t], al0, al1, al2, al3, b.x, b.y);
                MMA16816(acc[t], ah0, ah1, ah2, ah3, b.z, b.w);
            }
        }
        __syncthreads();
    }

    // ---- epilogue: v-partials = sum_n relu(D + bc1) * Wc2 ----
    float p0 = 0.0f, p1 = 0.0f;
    #pragma unroll
    for (int t = 0; t < NTILES_HALF; t++) {
        const int c0 = nh * 64 + t * 8 + (lane & 3) * 2;
        const float b0v = sp[P_BC1 + c0],     w0v = sp[P_WC2 + c0];
        const float b1v = sp[P_BC1 + c0 + 1], w1v = sp[P_WC2 + c0 + 1];
        p0 = fmaf(fmaxf(acc[t][0] + b0v, 0.0f), w0v, p0);
        p0 = fmaf(fmaxf(acc[t][1] + b1v, 0.0f), w1v, p0);
        p1 = fmaf(fmaxf(acc[t][2] + b0v, 0.0f), w0v, p1);
        p1 = fmaf(fmaxf(acc[t][3] + b1v, 0.0f), w1v, p1);
    }
    p0 += __shfl_xor_sync(0xffffffffu, p0, 1);
    p0 += __shfl_xor_sync(0xffffffffu, p0, 2);
    p1 += __shfl_xor_sync(0xffffffffu, p1, 1);
    p1 += __shfl_xor_sync(0xffffffffu, p1, 2);
    if ((lane & 3) == 0) {
        const int lr = mt * 16 + (lane >> 2);
        atomicAdd(&sp[P_VBUF + lr], p0);
        atomicAdd(&sp[P_VBUF + lr + 8], p1);
    }
    __syncthreads();
    if (tid < ROWS_CTA)
        v_out[row0 + tid] = sp[P_VBUF + tid] + sp[P_B + 7];
}

extern "C" void kernel_launch(void* const* d_in, const int* in_sizes, int n_in,
                              void* d_out, int out_size) {
    (void)in_sizes; (void)n_in; (void)out_size;
    const float* x    = (const float*)d_in[0];
    const float* w0   = (const float*)d_in[1];
    const float* b0   = (const float*)d_in[2];
    const float* w1   = (const float*)d_in[3];
    const float* b1   = (const float*)d_in[4];
    const float* w2   = (const float*)d_in[5];
    const float* b2   = (const float*)d_in[6];
    const float* leaf = (const float*)d_in[7];
    const float* Wc1  = (const float*)d_in[8];
    const float* bc1  = (const float*)d_in[9];
    const float* Wc2  = (const float*)d_in[10];
    const float* bc2  = (const float*)d_in[11];

    float* out   = (float*)d_out;
    float* p_out = out;
    float* v_out = out + (size_t)NB * 8;

    prep_w<<<(WFRAG_U32 + 255) / 256, 256>>>(Wc1);

    cudaFuncSetAttribute(ac_main, cudaFuncAttributeMaxDynamicSharedMemorySize, SMEM_BYTES);
    ac_main<<<NCTA, NTHREAD, SMEM_BYTES>>>(
        x, w0, b0, w1, b1, w2, b2, leaf, bc1, Wc2, bc2, p_out, v_out);
}

// round 5
// speedup vs baseline: 1.4007x; 1.4007x over previous
#include <cuda_runtime.h>
#include <cuda_bf16.h>
#include <cstdint>

#define NB 65536
#define FEAT 261
#define HID 128
#define KSTEPS 17                 // K padded to 272
#define NTHREAD 512
#define ROWS_CTA 256
#define NCTA (NB / ROWS_CTA)      // 256
#define NTILES_HALF 8

// W fragment scratch, hi/lo interleaved: [kstep][tile16][lane32][4 u32 = bh0,bh1,bl0,bl1]
#define WFRAG_U32 (KSTEPS * 16 * 32 * 4)      // 34816 u32 = 139264 B
__device__ __align__(16) uint32_t g_wfrag[WFRAG_U32];

// ---- smem layout ----
#define PARAM_FLOATS 1424
#define OFF_WF   (PARAM_FLOATS * 4)
#define SMEM_BYTES (OFF_WF + WFRAG_U32 * 4)   // 144960

// float indices inside params region
#define P_W0   0
#define P_W1   288
#define P_W2   554
#define P_LEAF 830
#define P_BC1  896
#define P_WC2  1024
#define P_B    1152
#define P_VBUF 1160   // 256 row partials -> ends 1416

// ======================= prep: Wc1 -> interleaved bf16 hi/lo fragments =======================
__global__ void __launch_bounds__(256) prep_w(const float* __restrict__ Wc1) {
    int idx = blockIdx.x * 256 + threadIdx.x;
    if (idx >= WFRAG_U32) return;
    int j    = idx & 3;            // 0,1: hi regs b0,b1 ; 2,3: lo regs b0,b1
    int lane = (idx >> 2) & 31;
    int t    = (idx >> 7) & 15;
    int s    = idx >> 11;
    int n = t * 8 + (lane >> 2);
    int k = s * 16 + (j & 1) * 8 + (lane & 3) * 2;
    float v0 = (k     < FEAT) ? Wc1[k * HID + n]       : 0.0f;
    float v1 = (k + 1 < FEAT) ? Wc1[(k + 1) * HID + n] : 0.0f;
    __nv_bfloat16 h0 = __float2bfloat16(v0), h1 = __float2bfloat16(v1);
    if (j < 2) {
        g_wfrag[idx] = ((uint32_t)__bfloat16_as_ushort(h1) << 16) | __bfloat16_as_ushort(h0);
    } else {
        __nv_bfloat16 l0 = __float2bfloat16(v0 - __bfloat162float(h0));
        __nv_bfloat16 l1 = __float2bfloat16(v1 - __bfloat162float(h1));
        g_wfrag[idx] = ((uint32_t)__bfloat16_as_ushort(l1) << 16) | __bfloat16_as_ushort(l0);
    }
}

// ======================= helpers =======================
__device__ __forceinline__ float warpsum(float v) {
    v += __shfl_xor_sync(0xffffffffu, v, 16);
    v += __shfl_xor_sync(0xffffffffu, v, 8);
    v += __shfl_xor_sync(0xffffffffu, v, 4);
    v += __shfl_xor_sync(0xffffffffu, v, 2);
    v += __shfl_xor_sync(0xffffffffu, v, 1);
    return v;
}
__device__ __forceinline__ float sigmoidf_fast(float g) { return 1.0f / (1.0f + __expf(-g)); }

// hi = packed truncated-bf16 of (v0,v1) via one PRMT; lo = round(v - hi) packed via cvt.rn.bf16x2
__device__ __forceinline__ uint32_t split_pair(float v0, float v1, uint32_t& lo) {
    uint32_t b0 = __float_as_uint(v0), b1 = __float_as_uint(v1), hi;
    asm("prmt.b32 %0, %1, %2, 0x7632;" : "=r"(hi) : "r"(b0), "r"(b1));
    float t0 = __uint_as_float(b0 & 0xFFFF0000u);
    float t1 = __uint_as_float(b1 & 0xFFFF0000u);
    float l0 = v0 - t0, l1 = v1 - t1;
    asm("cvt.rn.bf16x2.f32 %0, %1, %2;" : "=r"(lo) : "f"(l1), "f"(l0));
    return hi;
}

#define MMA16816(c, a0, a1, a2, a3, b0, b1) \
    asm volatile("mma.sync.aligned.m16n8k16.row.col.f32.bf16.bf16.f32 " \
        "{%0,%1,%2,%3}, {%4,%5,%6,%7}, {%8,%9}, {%0,%1,%2,%3};" \
        : "+f"((c)[0]), "+f"((c)[1]), "+f"((c)[2]), "+f"((c)[3]) \
        : "r"(a0), "r"(a1), "r"(a2), "r"(a3), "r"(b0), "r"(b1))

// ======================= main fused kernel =======================
__global__ void __launch_bounds__(NTHREAD, 1)
ac_main(const float* __restrict__ x,
        const float* __restrict__ w0, const float* __restrict__ b0,
        const float* __restrict__ w1, const float* __restrict__ b1,
        const float* __restrict__ w2, const float* __restrict__ b2,
        const float* __restrict__ leaf,
        const float* __restrict__ bc1,
        const float* __restrict__ Wc2, const float* __restrict__ bc2,
        float* __restrict__ p_out, float* __restrict__ v_out)
{
    extern __shared__ char smem[];
    float* sp = (float*)smem;
    const int tid  = threadIdx.x;
    const int lane = tid & 31;
    const int warp = tid >> 5;
    const int row0 = blockIdx.x * ROWS_CTA;

    // ---- stage params + W fragments ----
    for (int i = tid; i < 288; i += NTHREAD) sp[P_W0 + i] = (i < FEAT) ? w0[i] : 0.0f;
    for (int i = tid; i < 266; i += NTHREAD) sp[P_W1 + i] = w1[i];
    for (int i = tid; i < 276; i += NTHREAD) sp[P_W2 + i] = w2[i];
    if (tid < 64)  sp[P_LEAF + tid] = leaf[tid];
    if (tid < 128) sp[P_BC1 + tid]  = bc1[tid];
    if (tid < 128) sp[P_WC2 + tid]  = Wc2[tid];
    if (tid < 256) sp[P_VBUF + tid] = 0.0f;
    if (tid == 0) {
        sp[P_B + 0] = b0[0];
        sp[P_B + 1] = b1[0]; sp[P_B + 2] = b1[1];
        sp[P_B + 3] = b2[0]; sp[P_B + 4] = b2[1]; sp[P_B + 5] = b2[2]; sp[P_B + 6] = b2[3];
        sp[P_B + 7] = bc2[0];
    }
    {
        const uint4* g = (const uint4*)g_wfrag;
        uint4* s = (uint4*)(smem + OFF_WF);
        #pragma unroll 4
        for (int i = tid; i < WFRAG_U32 / 4; i += NTHREAD) s[i] = g[i];
    }
    __syncthreads();

    // ================= decision tree (exact fp32): 16 rows per warp =================
    {
        const int trow0 = row0 + warp * 16;
        #pragma unroll 1
        for (int r = 0; r < 16; r++) {
            const int row = trow0 + r;
            const float* xrow = x + (size_t)row * FEAT;
            float part = 0.0f;
            #pragma unroll
            for (int k = 0; k < 9; k++) {
                int f = lane + 32 * k;
                if (f < FEAT) part = fmaf(xrow[f], sp[P_W0 + f], part);
            }
            float gate = warpsum(part) + sp[P_B + 0];
            float cum  = sigmoidf_fast(gate);
            int node   = (gate >= 0.0f) ? 1 : 0;
            {
                const float* wr = sp + P_W1 + node * 133;
                const int s1 = 5 + node * 128;
                part = (lane < 5) ? xrow[lane] * wr[lane] : 0.0f;
                #pragma unroll
                for (int k = 0; k < 4; k++) { int j = lane + 32 * k; part = fmaf(xrow[s1 + j], wr[5 + j], part); }
                gate = warpsum(part) + sp[P_B + 1 + node];
                cum *= sigmoidf_fast(gate);
                node = node * 2 + ((gate >= 0.0f) ? 1 : 0);
            }
            {
                const float* wr = sp + P_W2 + node * 69;
                const int s2 = 5 + node * 64;
                part = (lane < 5) ? xrow[lane] * wr[lane] : 0.0f;
                #pragma unroll
                for (int k = 0; k < 2; k++) { int j = lane + 32 * k; part = fmaf(xrow[s2 + j], wr[5 + j], part); }
                gate = warpsum(part) + sp[P_B + 3 + node];
                cum *= sigmoidf_fast(gate);
                node = node * 2 + ((gate >= 0.0f) ? 1 : 0);
            }
            if (lane < 8)
                p_out[(size_t)row * 8 + lane] = cum * sp[P_LEAF + node * 8 + lane];
        }
    }

    // ================= critic GEMM: warp = m32 x n64, reg-converted A, prefetched =================
    const int mt = warp >> 1;          // 0..7 -> rows mt*32..mt*32+31
    const int nh = warp & 1;           // n-half
    const float* xbase = x + (size_t)(row0 + mt * 32 + (lane >> 2)) * FEAT;
    const int kb = (lane & 3) * 2;

    float acc[2][NTILES_HALF][4];
    #pragma unroll
    for (int m = 0; m < 2; m++)
        #pragma unroll
        for (int t = 0; t < NTILES_HALF; t++)
            #pragma unroll
            for (int j = 0; j < 4; j++) acc[m][t][j] = 0.0f;

    // A-fragment load: af[m*8 + {0..7}] = rows (r, r+8) x k (k0,k0+1,k0+8,k0+9)
    auto load_a = [&](float* af, int s, bool guard) {
        const int k0 = s * 16 + kb;
        #pragma unroll
        for (int m = 0; m < 2; m++) {
            const float* xr = xbase + (size_t)(m * 16) * FEAT;
            if (!guard) {
                af[m*8+0] = xr[k0];            af[m*8+1] = xr[k0+1];
                af[m*8+2] = xr[8*FEAT + k0];   af[m*8+3] = xr[8*FEAT + k0+1];
                af[m*8+4] = xr[k0+8];          af[m*8+5] = xr[k0+9];
                af[m*8+6] = xr[8*FEAT + k0+8]; af[m*8+7] = xr[8*FEAT + k0+9];
            } else {
                af[m*8+0] = (k0   < FEAT) ? xr[k0]   : 0.0f;
                af[m*8+1] = (k0+1 < FEAT) ? xr[k0+1] : 0.0f;
                af[m*8+2] = (k0   < FEAT) ? xr[8*FEAT + k0]   : 0.0f;
                af[m*8+3] = (k0+1 < FEAT) ? xr[8*FEAT + k0+1] : 0.0f;
                af[m*8+4] = (k0+8 < FEAT) ? xr[k0+8] : 0.0f;
                af[m*8+5] = (k0+9 < FEAT) ? xr[k0+9] : 0.0f;
                af[m*8+6] = (k0+8 < FEAT) ? xr[8*FEAT + k0+8] : 0.0f;
                af[m*8+7] = (k0+9 < FEAT) ? xr[8*FEAT + k0+9] : 0.0f;
            }
        }
    };

    uint32_t ah[2][4], al[2][4];
    {
        float af[16];
        load_a(af, 0, false);
        #pragma unroll
        for (int m = 0; m < 2; m++)
            #pragma unroll
            for (int p = 0; p < 4; p++)
                ah[m][p] = split_pair(af[m*8 + p*2], af[m*8 + p*2 + 1], al[m][p]);
    }

    const uint4* wf = (const uint4*)(smem + OFF_WF);

    #pragma unroll 1
    for (int s = 0; s < KSTEPS; s++) {
        float afn[16];
        if (s < KSTEPS - 1) load_a(afn, s + 1, s + 1 == KSTEPS - 1);

        const uint4* bp = wf + ((s * 16 + nh * NTILES_HALF) * 32 + lane);
        #pragma unroll
        for (int t = 0; t < NTILES_HALF; t++) {
            const uint4 b = bp[t * 32];
            #pragma unroll
            for (int m = 0; m < 2; m++) {
                MMA16816(acc[m][t], ah[m][0], ah[m][1], ah[m][2], ah[m][3], b.x, b.y);
                MMA16816(acc[m][t], al[m][0], al[m][1], al[m][2], al[m][3], b.x, b.y);
                MMA16816(acc[m][t], ah[m][0], ah[m][1], ah[m][2], ah[m][3], b.z, b.w);
            }
        }

        if (s < KSTEPS - 1) {
            #pragma unroll
            for (int m = 0; m < 2; m++)
                #pragma unroll
                for (int p = 0; p < 4; p++)
                    ah[m][p] = split_pair(afn[m*8 + p*2], afn[m*8 + p*2 + 1], al[m][p]);
        }
    }

    // ---- epilogue: v-partials = sum_n relu(D + bc1) * Wc2 ----
    #pragma unroll
    for (int m = 0; m < 2; m++) {
        float p0 = 0.0f, p1 = 0.0f;
        #pragma unroll
        for (int t = 0; t < NTILES_HALF; t++) {
            const int c0 = nh * 64 + t * 8 + (lane & 3) * 2;
            const float b0v = sp[P_BC1 + c0],     w0v = sp[P_WC2 + c0];
            const float b1v = sp[P_BC1 + c0 + 1], w1v = sp[P_WC2 + c0 + 1];
            p0 = fmaf(fmaxf(acc[m][t][0] + b0v, 0.0f), w0v, p0);
            p0 = fmaf(fmaxf(acc[m][t][1] + b1v, 0.0f), w1v, p0);
            p1 = fmaf(fmaxf(acc[m][t][2] + b0v, 0.0f), w0v, p1);
            p1 = fmaf(fmaxf(acc[m][t][3] + b1v, 0.0f), w1v, p1);
        }
        p0 += __shfl_xor_sync(0xffffffffu, p0, 1);
        p0 += __shfl_xor_sync(0xffffffffu, p0, 2);
        p1 += __shfl_xor_sync(0xffffffffu, p1, 1);
        p1 += __shfl_xor_sync(0xffffffffu, p1, 2);
        if ((lane & 3) == 0) {
            const int lr = mt * 32 + m * 16 + (lane >> 2);
            atomicAdd(&sp[P_VBUF + lr], p0);
            atomicAdd(&sp[P_VBUF + lr + 8], p1);
        }
    }
    __syncthreads();
    if (tid < ROWS_CTA)
        v_out[row0 + tid] = sp[P_VBUF + tid] + sp[P_B + 7];
}

extern "C" void kernel_launch(void* const* d_in, const int* in_sizes, int n_in,
                              void* d_out, int out_size) {
    (void)in_sizes; (void)n_in; (void)out_size;
    const float* x    = (const float*)d_in[0];
    const float* w0   = (const float*)d_in[1];
    const float* b0   = (const float*)d_in[2];
    const float* w1   = (const float*)d_in[3];
    const float* b1   = (const float*)d_in[4];
    const float* w2   = (const float*)d_in[5];
    const float* b2   = (const float*)d_in[6];
    const float* leaf = (const float*)d_in[7];
    const float* Wc1  = (const float*)d_in[8];
    const float* bc1  = (const float*)d_in[9];
    const float* Wc2  = (const float*)d_in[10];
    const float* bc2  = (const float*)d_in[11];

    float* out   = (float*)d_out;
    float* p_out = out;
    float* v_out = out + (size_t)NB * 8;

    prep_w<<<(WFRAG_U32 + 255) / 256, 256>>>(Wc1);

    cudaFuncSetAttribute(ac_main, cudaFuncAttributeMaxDynamicSharedMemorySize, SMEM_BYTES);
    ac_main<<<NCTA, NTHREAD, SMEM_BYTES>>>(
        x, w0, b0, w1, b1, w2, b2, leaf, bc1, Wc2, bc2, p_out, v_out);
}